// round 1
// baseline (speedup 1.0000x reference)
#include <cuda_runtime.h>
#include <cstdint>

#define NB 2
#define NS 4096
#define NH 8
#define NDH 64
#define ND 512
#define NBH (NB*NH)

// Scratch (allocation-free rule: __device__ globals)
__device__ float g_Q[(size_t)NBH * NS * NDH];
__device__ float g_K[(size_t)NBH * NS * NDH];
__device__ float g_V[(size_t)NBH * NS * NDH];
__device__ float g_attn[(size_t)NB * NS * ND];

__device__ __forceinline__ uint32_t f2tf32(float v) {
    uint32_t u;
    asm("cvt.rna.tf32.f32 %0, %1;" : "=r"(u) : "f"(v));
    return u;
}

// D = A(16x8) * B(8x8) + D, tf32 inputs, f32 accum
__device__ __forceinline__ void mma_tf32(float* c, const uint32_t* a, const uint32_t* b) {
    asm volatile(
        "mma.sync.aligned.m16n8k8.row.col.f32.tf32.tf32.f32 "
        "{%0,%1,%2,%3}, {%4,%5,%6,%7}, {%8,%9}, {%0,%1,%2,%3};\n"
        : "+f"(c[0]), "+f"(c[1]), "+f"(c[2]), "+f"(c[3])
        : "r"(a[0]), "r"(a[1]), "r"(a[2]), "r"(a[3]), "r"(b[0]), "r"(b[1]));
}

// ---------------------------------------------------------------------------
// GEMM: out[m,n] = sum_k A[m,k] * W[n,k]   (torch Linear, W row-major [N,K])
// CTA tile 64x64, 4 warps (each 16 rows x 64 cols), BK=32.
// MODE 0: A = x, blockIdx.z selects {Wq,Wk,Wv}; writes head-split [B,H,S,Dh]
//         layout into g_Q/g_K/g_V; Q scaled by 0.125 (= Dh^-0.5, exact pow2).
// MODE 1: A = g_attn; W = Wo; writes row-major [M,512] + bias into out.
// ---------------------------------------------------------------------------
template <int MODE>
__global__ __launch_bounds__(128) void gemm_kernel(
    const float* __restrict__ A,
    const float* __restrict__ W0, const float* __restrict__ W1,
    const float* __restrict__ W2,
    const float* __restrict__ bias, float* __restrict__ out)
{
    __shared__ float As[64][36];  // stride 36: bank = (4g+t)%32, conflict-free frags
    __shared__ float Bs[64][36];

    const int tid = threadIdx.x;
    const int warp = tid >> 5, lane = tid & 31, g = lane >> 2, t = lane & 3;
    const int m0 = blockIdx.x * 64, n0 = blockIdx.y * 64;

    const float* Ap = (MODE == 0) ? A : g_attn;
    const float* W = (MODE == 1) ? W0
                     : (blockIdx.z == 0 ? W0 : (blockIdx.z == 1 ? W1 : W2));

    float acc[8][4];
#pragma unroll
    for (int n = 0; n < 8; n++)
#pragma unroll
        for (int i = 0; i < 4; i++) acc[n][i] = 0.f;

    for (int kt = 0; kt < ND / 32; kt++) {
#pragma unroll
        for (int i = 0; i < 4; i++) {
            int idx = tid + i * 128;            // 512 float4 per tile
            int r = idx >> 3, c4 = (idx & 7) << 2;
            *(float4*)(&As[r][c4]) =
                *(const float4*)(Ap + (size_t)(m0 + r) * ND + kt * 32 + c4);
            *(float4*)(&Bs[r][c4]) =
                *(const float4*)(W + (size_t)(n0 + r) * ND + kt * 32 + c4);
        }
        __syncthreads();
#pragma unroll
        for (int ks = 0; ks < 4; ks++) {
            const int row = warp * 16 + g, col = ks * 8 + t;
            uint32_t a[4];
            a[0] = f2tf32(As[row][col]);
            a[1] = f2tf32(As[row + 8][col]);
            a[2] = f2tf32(As[row][col + 4]);
            a[3] = f2tf32(As[row + 8][col + 4]);
#pragma unroll
            for (int n = 0; n < 8; n++) {
                uint32_t b[2];
                b[0] = f2tf32(Bs[n * 8 + g][col]);
                b[1] = f2tf32(Bs[n * 8 + g][col + 4]);
                mma_tf32(acc[n], a, b);
            }
        }
        __syncthreads();
    }

    const int r = m0 + warp * 16 + g;
    if (MODE == 0) {
        float* dst = blockIdx.z == 0 ? g_Q : (blockIdx.z == 1 ? g_K : g_V);
        const float scl = (blockIdx.z == 0) ? 0.125f : 1.0f;
        const int bb = r >> 12, ss = r & (NS - 1);
#pragma unroll
        for (int n = 0; n < 8; n++) {
            const int c = n0 + n * 8 + 2 * t;
            const int hh = c >> 6, dd = c & 63;
            const size_t base = (((size_t)(bb * NH + hh)) * NS + ss) * NDH + dd;
            dst[base] = acc[n][0] * scl;
            dst[base + 1] = acc[n][1] * scl;
            dst[base + 8 * NDH] = acc[n][2] * scl;
            dst[base + 8 * NDH + 1] = acc[n][3] * scl;
        }
    } else {
#pragma unroll
        for (int n = 0; n < 8; n++) {
            const int c = n0 + n * 8 + 2 * t;
            const float b0v = bias[c], b1v = bias[c + 1];
            out[(size_t)r * ND + c] = acc[n][0] + b0v;
            out[(size_t)r * ND + c + 1] = acc[n][1] + b1v;
            out[(size_t)(r + 8) * ND + c] = acc[n][2] + b0v;
            out[(size_t)(r + 8) * ND + c + 1] = acc[n][3] + b1v;
        }
    }
}

// ---------------------------------------------------------------------------
// Flash attention: grid (S/64, B*H), 128 threads (4 warps, 16 Q-rows each).
// Streams 64-row KV tiles, online softmax, tf32 mma for QK^T and PV.
// Q already scaled by Dh^-0.5.
// ---------------------------------------------------------------------------
#define QK_STRIDE 68   // (4g+t)%32 distinct for A/B frags
#define V_STRIDE  72   // (8t+g)%32 distinct for V B-frags
#define FLASH_SMEM ((3 * 64 * QK_STRIDE + 64 * V_STRIDE) * sizeof(float))

__global__ __launch_bounds__(128) void flash_kernel() {
    extern __shared__ float smf[];
    float* Qs = smf;
    float* Ks = smf + 64 * QK_STRIDE;
    float* Vs = smf + 2 * 64 * QK_STRIDE;
    float* Ps = smf + 2 * 64 * QK_STRIDE + 64 * V_STRIDE;

    const int tid = threadIdx.x;
    const int warp = tid >> 5, lane = tid & 31, g = lane >> 2, t = lane & 3;
    const int bh = blockIdx.y, qt = blockIdx.x;
    const int row = warp * 16 + g;

    const float* Qg = g_Q + (size_t)(bh * NS + qt * 64) * NDH;
    const float* Kg = g_K + (size_t)bh * NS * NDH;
    const float* Vg = g_V + (size_t)bh * NS * NDH;

#pragma unroll
    for (int i = 0; i < 8; i++) {
        int idx = tid + i * 128;                 // 1024 float4
        int r = idx >> 4, c4 = (idx & 15) << 2;
        *(float4*)(Qs + r * QK_STRIDE + c4) = *(const float4*)(Qg + r * NDH + c4);
    }

    float o[8][4];
#pragma unroll
    for (int n = 0; n < 8; n++)
#pragma unroll
        for (int i = 0; i < 4; i++) o[n][i] = 0.f;
    float m0 = -1e30f, m1 = -1e30f, l0 = 0.f, l1 = 0.f;
    __syncthreads();

    for (int j = 0; j < NS / 64; j++) {
        const float* kp = Kg + (size_t)j * 64 * NDH;
        const float* vp = Vg + (size_t)j * 64 * NDH;
#pragma unroll
        for (int i = 0; i < 8; i++) {
            int idx = tid + i * 128;
            int r = idx >> 4, c4 = (idx & 15) << 2;
            *(float4*)(Ks + r * QK_STRIDE + c4) = *(const float4*)(kp + r * NDH + c4);
            *(float4*)(Vs + r * V_STRIDE + c4) = *(const float4*)(vp + r * NDH + c4);
        }
        __syncthreads();

        // S = Q K^T  (16x64 per warp)
        float s[8][4];
#pragma unroll
        for (int n = 0; n < 8; n++)
#pragma unroll
            for (int i = 0; i < 4; i++) s[n][i] = 0.f;
#pragma unroll
        for (int ks = 0; ks < 8; ks++) {
            const int col = ks * 8 + t;
            uint32_t a[4];
            a[0] = f2tf32(Qs[row * QK_STRIDE + col]);
            a[1] = f2tf32(Qs[(row + 8) * QK_STRIDE + col]);
            a[2] = f2tf32(Qs[row * QK_STRIDE + col + 4]);
            a[3] = f2tf32(Qs[(row + 8) * QK_STRIDE + col + 4]);
#pragma unroll
            for (int n = 0; n < 8; n++) {
                uint32_t b[2];
                b[0] = f2tf32(Ks[(n * 8 + g) * QK_STRIDE + col]);
                b[1] = f2tf32(Ks[(n * 8 + g) * QK_STRIDE + col + 4]);
                mma_tf32(s[n], a, b);
            }
        }

        // online softmax (rows: row -> stats0, row+8 -> stats1)
        float mx0 = -1e30f, mx1 = -1e30f;
#pragma unroll
        for (int n = 0; n < 8; n++) {
            mx0 = fmaxf(mx0, fmaxf(s[n][0], s[n][1]));
            mx1 = fmaxf(mx1, fmaxf(s[n][2], s[n][3]));
        }
        mx0 = fmaxf(mx0, __shfl_xor_sync(0xffffffffu, mx0, 1));
        mx0 = fmaxf(mx0, __shfl_xor_sync(0xffffffffu, mx0, 2));
        mx1 = fmaxf(mx1, __shfl_xor_sync(0xffffffffu, mx1, 1));
        mx1 = fmaxf(mx1, __shfl_xor_sync(0xffffffffu, mx1, 2));
        const float mn0 = fmaxf(m0, mx0), mn1 = fmaxf(m1, mx1);
        const float sc0 = __expf(m0 - mn0), sc1 = __expf(m1 - mn1);

        float ps0 = 0.f, ps1 = 0.f;
#pragma unroll
        for (int n = 0; n < 8; n++) {
            const float p0 = __expf(s[n][0] - mn0);
            const float p1 = __expf(s[n][1] - mn0);
            const float p2 = __expf(s[n][2] - mn1);
            const float p3 = __expf(s[n][3] - mn1);
            ps0 += p0 + p1;
            ps1 += p2 + p3;
            const int c = n * 8 + 2 * t;
            *(float2*)(Ps + row * QK_STRIDE + c) = make_float2(p0, p1);
            *(float2*)(Ps + (row + 8) * QK_STRIDE + c) = make_float2(p2, p3);
            o[n][0] *= sc0; o[n][1] *= sc0;
            o[n][2] *= sc1; o[n][3] *= sc1;
        }
        ps0 += __shfl_xor_sync(0xffffffffu, ps0, 1);
        ps0 += __shfl_xor_sync(0xffffffffu, ps0, 2);
        ps1 += __shfl_xor_sync(0xffffffffu, ps1, 1);
        ps1 += __shfl_xor_sync(0xffffffffu, ps1, 2);
        l0 = l0 * sc0 + ps0;
        l1 = l1 * sc1 + ps1;
        m0 = mn0;
        m1 = mn1;
        __syncwarp();   // Ps is warp-private rows; order STS before LDS

        // O += P V   (k-dim = kv tile of 64)
#pragma unroll
        for (int ks = 0; ks < 8; ks++) {
            const int col = ks * 8 + t;
            uint32_t a[4];
            a[0] = f2tf32(Ps[row * QK_STRIDE + col]);
            a[1] = f2tf32(Ps[(row + 8) * QK_STRIDE + col]);
            a[2] = f2tf32(Ps[row * QK_STRIDE + col + 4]);
            a[3] = f2tf32(Ps[(row + 8) * QK_STRIDE + col + 4]);
#pragma unroll
            for (int n = 0; n < 8; n++) {
                uint32_t b[2];
                b[0] = f2tf32(Vs[(ks * 8 + t) * V_STRIDE + n * 8 + g]);
                b[1] = f2tf32(Vs[(ks * 8 + t + 4) * V_STRIDE + n * 8 + g]);
                mma_tf32(o[n], a, b);
            }
        }
        __syncthreads();   // done reading K/V/P before next tile's loads
    }

    const float inv0 = 1.f / l0, inv1 = 1.f / l1;
    const int bb = bh >> 3, hh = bh & 7;
    const int r0 = qt * 64 + row;
    float* og = g_attn + ((size_t)bb * NS + r0) * ND + hh * NDH;
#pragma unroll
    for (int n = 0; n < 8; n++) {
        const int c = n * 8 + 2 * t;
        *(float2*)(og + c) = make_float2(o[n][0] * inv0, o[n][1] * inv0);
        *(float2*)(og + 8 * ND + c) = make_float2(o[n][2] * inv1, o[n][3] * inv1);
    }
}

// ---------------------------------------------------------------------------
extern "C" void kernel_launch(void* const* d_in, const int* in_sizes, int n_in,
                              void* d_out, int out_size) {
    const float* x  = (const float*)d_in[0];
    const float* Wq = (const float*)d_in[1];
    const float* Wk = (const float*)d_in[2];
    const float* Wv = (const float*)d_in[3];
    const float* Wo = (const float*)d_in[4];
    const float* bo = (const float*)d_in[5];
    float* out = (float*)d_out;

    cudaFuncSetAttribute(flash_kernel, cudaFuncAttributeMaxDynamicSharedMemorySize,
                         (int)FLASH_SMEM);

    // 1) Q,K,V = x @ {Wq,Wk,Wv}^T  -> head-split scratch (Q pre-scaled)
    gemm_kernel<0><<<dim3(128, 8, 3), 128>>>(x, Wq, Wk, Wv, nullptr, nullptr);
    // 2) flash attention -> g_attn [B,S,D]
    flash_kernel<<<dim3(NS / 64, NBH), 128, FLASH_SMEM>>>();
    // 3) out = g_attn @ Wo^T + bo
    gemm_kernel<1><<<dim3(128, 8, 1), 128>>>(nullptr, Wo, nullptr, nullptr, bo, out);
}

// round 2
// speedup vs baseline: 1.0005x; 1.0005x over previous
#include <cuda_runtime.h>
#include <cstdint>

#define NB 2
#define NS 4096
#define NH 8
#define NDH 64
#define ND 512
#define NBH (NB*NH)

// Scratch (allocation-free rule: __device__ globals)
__device__ float g_Q[(size_t)NBH * NS * NDH];
__device__ float g_K[(size_t)NBH * NS * NDH];
__device__ float g_V[(size_t)NBH * NS * NDH];
__device__ float g_attn[(size_t)NB * NS * ND];

__device__ __forceinline__ uint32_t f2tf32(float v) {
    uint32_t u;
    asm("cvt.rna.tf32.f32 %0, %1;" : "=r"(u) : "f"(v));
    return u;
}

// D = A(16x8) * B(8x8) + D, tf32 inputs, f32 accum
__device__ __forceinline__ void mma_tf32(float* c, const uint32_t* a, const uint32_t* b) {
    asm volatile(
        "mma.sync.aligned.m16n8k8.row.col.f32.tf32.tf32.f32 "
        "{%0,%1,%2,%3}, {%4,%5,%6,%7}, {%8,%9}, {%0,%1,%2,%3};\n"
        : "+f"(c[0]), "+f"(c[1]), "+f"(c[2]), "+f"(c[3])
        : "r"(a[0]), "r"(a[1]), "r"(a[2]), "r"(a[3]), "r"(b[0]), "r"(b[1]));
}

// ---------------------------------------------------------------------------
// GEMM: out[m,n] = sum_k A[m,k] * W[n,k]   (torch Linear, W row-major [N,K])
// CTA tile 64x64, 4 warps (each 16 rows x 64 cols), BK=32.
// MODE 0: A = x, blockIdx.z selects {Wq,Wk,Wv}; writes head-split [B,H,S,Dh]
//         layout into g_Q/g_K/g_V; Q scaled by 0.125 (= Dh^-0.5, exact pow2).
// MODE 1: A = g_attn; W = Wo; writes row-major [M,512] + bias into out.
// ---------------------------------------------------------------------------
template <int MODE>
__global__ __launch_bounds__(128) void gemm_kernel(
    const float* __restrict__ A,
    const float* __restrict__ W0, const float* __restrict__ W1,
    const float* __restrict__ W2,
    const float* __restrict__ bias, float* __restrict__ out)
{
    __shared__ float As[64][36];  // stride 36: bank = (4g+t)%32, conflict-free frags
    __shared__ float Bs[64][36];

    const int tid = threadIdx.x;
    const int warp = tid >> 5, lane = tid & 31, g = lane >> 2, t = lane & 3;
    const int m0 = blockIdx.x * 64, n0 = blockIdx.y * 64;

    const float* Ap = (MODE == 0) ? A : g_attn;
    const float* W = (MODE == 1) ? W0
                     : (blockIdx.z == 0 ? W0 : (blockIdx.z == 1 ? W1 : W2));

    float acc[8][4];
#pragma unroll
    for (int n = 0; n < 8; n++)
#pragma unroll
        for (int i = 0; i < 4; i++) acc[n][i] = 0.f;

    for (int kt = 0; kt < ND / 32; kt++) {
#pragma unroll
        for (int i = 0; i < 4; i++) {
            int idx = tid + i * 128;            // 512 float4 per tile
            int r = idx >> 3, c4 = (idx & 7) << 2;
            *(float4*)(&As[r][c4]) =
                *(const float4*)(Ap + (size_t)(m0 + r) * ND + kt * 32 + c4);
            *(float4*)(&Bs[r][c4]) =
                *(const float4*)(W + (size_t)(n0 + r) * ND + kt * 32 + c4);
        }
        __syncthreads();
#pragma unroll
        for (int ks = 0; ks < 4; ks++) {
            const int row = warp * 16 + g, col = ks * 8 + t;
            uint32_t a[4];
            a[0] = f2tf32(As[row][col]);
            a[1] = f2tf32(As[row + 8][col]);
            a[2] = f2tf32(As[row][col + 4]);
            a[3] = f2tf32(As[row + 8][col + 4]);
#pragma unroll
            for (int n = 0; n < 8; n++) {
                uint32_t b[2];
                b[0] = f2tf32(Bs[n * 8 + g][col]);
                b[1] = f2tf32(Bs[n * 8 + g][col + 4]);
                mma_tf32(acc[n], a, b);
            }
        }
        __syncthreads();
    }

    const int r = m0 + warp * 16 + g;
    if (MODE == 0) {
        float* dst = blockIdx.z == 0 ? g_Q : (blockIdx.z == 1 ? g_K : g_V);
        const float scl = (blockIdx.z == 0) ? 0.125f : 1.0f;
        const int bb = r >> 12, ss = r & (NS - 1);
#pragma unroll
        for (int n = 0; n < 8; n++) {
            const int c = n0 + n * 8 + 2 * t;
            const int hh = c >> 6, dd = c & 63;
            const size_t base = (((size_t)(bb * NH + hh)) * NS + ss) * NDH + dd;
            dst[base] = acc[n][0] * scl;
            dst[base + 1] = acc[n][1] * scl;
            dst[base + 8 * NDH] = acc[n][2] * scl;
            dst[base + 8 * NDH + 1] = acc[n][3] * scl;
        }
    } else {
#pragma unroll
        for (int n = 0; n < 8; n++) {
            const int c = n0 + n * 8 + 2 * t;
            const float b0v = bias[c], b1v = bias[c + 1];
            out[(size_t)r * ND + c] = acc[n][0] + b0v;
            out[(size_t)r * ND + c + 1] = acc[n][1] + b1v;
            out[(size_t)(r + 8) * ND + c] = acc[n][2] + b0v;
            out[(size_t)(r + 8) * ND + c + 1] = acc[n][3] + b1v;
        }
    }
}

// ---------------------------------------------------------------------------
// Flash attention: grid (S/64, B*H), 128 threads (4 warps, 16 Q-rows each).
// Streams 64-row KV tiles, online softmax, tf32 mma for QK^T and PV.
// Q already scaled by Dh^-0.5.
// ---------------------------------------------------------------------------
#define QK_STRIDE 68   // (4g+t)%32 distinct for A/B frags
#define V_STRIDE  72   // (8t+g)%32 distinct for V B-frags
#define FLASH_SMEM ((3 * 64 * QK_STRIDE + 64 * V_STRIDE) * sizeof(float))

__global__ __launch_bounds__(128) void flash_kernel() {
    extern __shared__ float smf[];
    float* Qs = smf;
    float* Ks = smf + 64 * QK_STRIDE;
    float* Vs = smf + 2 * 64 * QK_STRIDE;
    float* Ps = smf + 2 * 64 * QK_STRIDE + 64 * V_STRIDE;

    const int tid = threadIdx.x;
    const int warp = tid >> 5, lane = tid & 31, g = lane >> 2, t = lane & 3;
    const int bh = blockIdx.y, qt = blockIdx.x;
    const int row = warp * 16 + g;

    const float* Qg = g_Q + (size_t)(bh * NS + qt * 64) * NDH;
    const float* Kg = g_K + (size_t)bh * NS * NDH;
    const float* Vg = g_V + (size_t)bh * NS * NDH;

#pragma unroll
    for (int i = 0; i < 8; i++) {
        int idx = tid + i * 128;                 // 1024 float4
        int r = idx >> 4, c4 = (idx & 15) << 2;
        *(float4*)(Qs + r * QK_STRIDE + c4) = *(const float4*)(Qg + r * NDH + c4);
    }

    float o[8][4];
#pragma unroll
    for (int n = 0; n < 8; n++)
#pragma unroll
        for (int i = 0; i < 4; i++) o[n][i] = 0.f;
    float m0 = -1e30f, m1 = -1e30f, l0 = 0.f, l1 = 0.f;
    __syncthreads();

    for (int j = 0; j < NS / 64; j++) {
        const float* kp = Kg + (size_t)j * 64 * NDH;
        const float* vp = Vg + (size_t)j * 64 * NDH;
#pragma unroll
        for (int i = 0; i < 8; i++) {
            int idx = tid + i * 128;
            int r = idx >> 4, c4 = (idx & 15) << 2;
            *(float4*)(Ks + r * QK_STRIDE + c4) = *(const float4*)(kp + r * NDH + c4);
            *(float4*)(Vs + r * V_STRIDE + c4) = *(const float4*)(vp + r * NDH + c4);
        }
        __syncthreads();

        // S = Q K^T  (16x64 per warp)
        float s[8][4];
#pragma unroll
        for (int n = 0; n < 8; n++)
#pragma unroll
            for (int i = 0; i < 4; i++) s[n][i] = 0.f;
#pragma unroll
        for (int ks = 0; ks < 8; ks++) {
            const int col = ks * 8 + t;
            uint32_t a[4];
            a[0] = f2tf32(Qs[row * QK_STRIDE + col]);
            a[1] = f2tf32(Qs[(row + 8) * QK_STRIDE + col]);
            a[2] = f2tf32(Qs[row * QK_STRIDE + col + 4]);
            a[3] = f2tf32(Qs[(row + 8) * QK_STRIDE + col + 4]);
#pragma unroll
            for (int n = 0; n < 8; n++) {
                uint32_t b[2];
                b[0] = f2tf32(Ks[(n * 8 + g) * QK_STRIDE + col]);
                b[1] = f2tf32(Ks[(n * 8 + g) * QK_STRIDE + col + 4]);
                mma_tf32(s[n], a, b);
            }
        }

        // online softmax (rows: row -> stats0, row+8 -> stats1)
        float mx0 = -1e30f, mx1 = -1e30f;
#pragma unroll
        for (int n = 0; n < 8; n++) {
            mx0 = fmaxf(mx0, fmaxf(s[n][0], s[n][1]));
            mx1 = fmaxf(mx1, fmaxf(s[n][2], s[n][3]));
        }
        mx0 = fmaxf(mx0, __shfl_xor_sync(0xffffffffu, mx0, 1));
        mx0 = fmaxf(mx0, __shfl_xor_sync(0xffffffffu, mx0, 2));
        mx1 = fmaxf(mx1, __shfl_xor_sync(0xffffffffu, mx1, 1));
        mx1 = fmaxf(mx1, __shfl_xor_sync(0xffffffffu, mx1, 2));
        const float mn0 = fmaxf(m0, mx0), mn1 = fmaxf(m1, mx1);
        const float sc0 = __expf(m0 - mn0), sc1 = __expf(m1 - mn1);

        float ps0 = 0.f, ps1 = 0.f;
#pragma unroll
        for (int n = 0; n < 8; n++) {
            const float p0 = __expf(s[n][0] - mn0);
            const float p1 = __expf(s[n][1] - mn0);
            const float p2 = __expf(s[n][2] - mn1);
            const float p3 = __expf(s[n][3] - mn1);
            ps0 += p0 + p1;
            ps1 += p2 + p3;
            const int c = n * 8 + 2 * t;
            *(float2*)(Ps + row * QK_STRIDE + c) = make_float2(p0, p1);
            *(float2*)(Ps + (row + 8) * QK_STRIDE + c) = make_float2(p2, p3);
            o[n][0] *= sc0; o[n][1] *= sc0;
            o[n][2] *= sc1; o[n][3] *= sc1;
        }
        ps0 += __shfl_xor_sync(0xffffffffu, ps0, 1);
        ps0 += __shfl_xor_sync(0xffffffffu, ps0, 2);
        ps1 += __shfl_xor_sync(0xffffffffu, ps1, 1);
        ps1 += __shfl_xor_sync(0xffffffffu, ps1, 2);
        l0 = l0 * sc0 + ps0;
        l1 = l1 * sc1 + ps1;
        m0 = mn0;
        m1 = mn1;
        __syncwarp();   // Ps is warp-private rows; order STS before LDS

        // O += P V   (k-dim = kv tile of 64)
#pragma unroll
        for (int ks = 0; ks < 8; ks++) {
            const int col = ks * 8 + t;
            uint32_t a[4];
            a[0] = f2tf32(Ps[row * QK_STRIDE + col]);
            a[1] = f2tf32(Ps[(row + 8) * QK_STRIDE + col]);
            a[2] = f2tf32(Ps[row * QK_STRIDE + col + 4]);
            a[3] = f2tf32(Ps[(row + 8) * QK_STRIDE + col + 4]);
#pragma unroll
            for (int n = 0; n < 8; n++) {
                uint32_t b[2];
                b[0] = f2tf32(Vs[(ks * 8 + t) * V_STRIDE + n * 8 + g]);
                b[1] = f2tf32(Vs[(ks * 8 + t + 4) * V_STRIDE + n * 8 + g]);
                mma_tf32(o[n], a, b);
            }
        }
        __syncthreads();   // done reading K/V/P before next tile's loads
    }

    const float inv0 = 1.f / l0, inv1 = 1.f / l1;
    const int bb = bh >> 3, hh = bh & 7;
    const int r0 = qt * 64 + row;
    float* og = g_attn + ((size_t)bb * NS + r0) * ND + hh * NDH;
#pragma unroll
    for (int n = 0; n < 8; n++) {
        const int c = n * 8 + 2 * t;
        *(float2*)(og + c) = make_float2(o[n][0] * inv0, o[n][1] * inv0);
        *(float2*)(og + 8 * ND + c) = make_float2(o[n][2] * inv1, o[n][3] * inv1);
    }
}

// ---------------------------------------------------------------------------
extern "C" void kernel_launch(void* const* d_in, const int* in_sizes, int n_in,
                              void* d_out, int out_size) {
    const float* x  = (const float*)d_in[0];
    const float* Wq = (const float*)d_in[1];
    const float* Wk = (const float*)d_in[2];
    const float* Wv = (const float*)d_in[3];
    const float* Wo = (const float*)d_in[4];
    const float* bo = (const float*)d_in[5];
    float* out = (float*)d_out;

    cudaFuncSetAttribute(flash_kernel, cudaFuncAttributeMaxDynamicSharedMemorySize,
                         (int)FLASH_SMEM);

    // 1) Q,K,V = x @ {Wq,Wk,Wv}^T  -> head-split scratch (Q pre-scaled)
    gemm_kernel<0><<<dim3(128, 8, 3), 128>>>(x, Wq, Wk, Wv, nullptr, nullptr);
    // 2) flash attention -> g_attn [B,S,D]
    flash_kernel<<<dim3(NS / 64, NBH), 128, FLASH_SMEM>>>();
    // 3) out = g_attn @ Wo^T + bo
    gemm_kernel<1><<<dim3(128, 8, 1), 128>>>(nullptr, Wo, nullptr, nullptr, bo, out);
}